// round 16
// baseline (speedup 1.0000x reference)
#include <cuda_runtime.h>
#include <cuda_fp16.h>

// Triplane sampling, GB300 (sm_103a). Persistent-gather design:
//   side stream 1: transpose s3  (fp32->fp16, 339MB) -> notify g_s3
//   side stream 2: transpose s0,s1,s2                -> notify g_small
//   capture stream: persistent gather_k (444 blocks, fully resident):
//     wait g_small -> phase A (grid-stride): sample s0-2, write out blocks 0-2
//     wait g_s3    -> phase B (grid-stride): recompute s0-2 + s3, write block 3
// fp16 channel-major scratch [scale][plane][texel][72] halves (150 MB).

#define CDIM 72
#define NCHUNK_H 9            // 72 / 8 halves per uint4 chunk
#define THREADS_PER_PT 27     // 3 planes * 9 chunks
#define S3_TOTAL    12288     // (512*512/64)*3 transpose blocks
#define SMALL_TOTAL 4032      // ((64^2+128^2+256^2)/64)*3
#define GATHER_BLOCKS 444     // 3 per SM * 148 SMs, guaranteed resident

__device__ __half g_tph[75202560];   // 150.4 MB fp16 scratch, channel-major
__device__ int    g_s3    = 0;       // s3 transpose blocks completed
__device__ int    g_small = 0;       // small transpose blocks completed
__device__ int    g_fin   = 0;       // gather blocks completed (for reset)

__device__ __forceinline__ unsigned h2_bits(__half2 h) {
    union { __half2 h; unsigned u; } cv;
    cv.h = h;
    return cv.u;
}

// ---------------- transpose: [3,72,r2] fp32 -> [3, r2, 72] fp16 ----------------
// Block = one plane x 64 texels x 72 channels, 288 threads.
__global__ __launch_bounds__(288) void transpose_k(
    const float* __restrict__ in, int off, int r2, int* ctr)
{
    __shared__ unsigned tile[36 * 68];   // [ch-pair][texel], row pad 68
    const int p   = blockIdx.y;
    const int t0  = blockIdx.x * 64;
    const int tid = threadIdx.x;

    const float* src = in + (size_t)p * CDIM * r2 + t0;
    #pragma unroll
    for (int i = 0; i < 2; i++) {
        int idx = i * 288 + tid;         // 0..575
        int v   = idx & 15;              // texel quad 0..15
        int cp  = idx >> 4;              // channel pair 0..35
        const float* sp = src + (size_t)(2 * cp) * r2 + 4 * v;
        float4 a = __ldg((const float4*)sp);
        float4 b = __ldg((const float4*)(sp + r2));
        uint4 o;
        o.x = h2_bits(__floats2half2_rn(a.x, b.x));
        o.y = h2_bits(__floats2half2_rn(a.y, b.y));
        o.z = h2_bits(__floats2half2_rn(a.z, b.z));
        o.w = h2_bits(__floats2half2_rn(a.w, b.w));
        *(uint4*)&tile[cp * 68 + 4 * v] = o;
    }
    __syncthreads();

    uint4* dst = (uint4*)(g_tph + off) + ((size_t)p * r2 + t0) * NCHUNK_H;
    #pragma unroll
    for (int i = 0; i < 2; i++) {
        int lin = i * 288 + tid;         // 0..575
        int x = lin / NCHUNK_H;          // texel 0..63
        int q = lin - x * NCHUNK_H;      // uint4 index 0..8
        uint4 o;
        o.x = tile[(4 * q + 0) * 68 + x];
        o.y = tile[(4 * q + 1) * 68 + x];
        o.z = tile[(4 * q + 2) * 68 + x];
        o.w = tile[(4 * q + 3) * 68 + x];
        dst[lin] = o;
    }

    __syncthreads();
    if (tid == 0) {
        __threadfence();
        atomicAdd(ctr, 1);
    }
}

// ---------------- bilinear corner fetch for one scale ----------------
__device__ __forceinline__ void sample_scale(
    int p, int k, float cx, float cy, int r, const __half* __restrict__ base,
    float* acc)
{
    const float rm1 = (float)(r - 1);
    float fx = (cx + 1.0f) * 0.5f * rm1;
    float fy = (cy + 1.0f) * 0.5f * rm1;
    fx = fminf(fmaxf(fx, 0.0f), rm1);
    fy = fminf(fmaxf(fy, 0.0f), rm1);

    const float x0f = floorf(fx);
    const float y0f = floorf(fy);
    const float wx = fx - x0f;
    const float wy = fy - y0f;
    const int x0 = (int)x0f;
    const int y0 = (int)y0f;
    const int x1 = min(x0 + 1, r - 1);
    const int y1 = min(y0 + 1, r - 1);

    const unsigned row0 = (unsigned)(p * r + y0) * (unsigned)r;
    const unsigned row1 = (unsigned)(p * r + y1) * (unsigned)r;

    const uint4 u00 = __ldg((const uint4*)(base + (size_t)(row0 + x0) * CDIM) + k);
    const uint4 u01 = __ldg((const uint4*)(base + (size_t)(row0 + x1) * CDIM) + k);
    const uint4 u10 = __ldg((const uint4*)(base + (size_t)(row1 + x0) * CDIM) + k);
    const uint4 u11 = __ldg((const uint4*)(base + (size_t)(row1 + x1) * CDIM) + k);

    const float w00 = (1.0f - wx) * (1.0f - wy);
    const float w01 = wx * (1.0f - wy);
    const float w10 = (1.0f - wx) * wy;
    const float w11 = wx * wy;

    #pragma unroll
    for (int h = 0; h < 4; h++) {
        const unsigned a00 = (&u00.x)[h], a01 = (&u01.x)[h];
        const unsigned a10 = (&u10.x)[h], a11 = (&u11.x)[h];
        float2 f00 = __half22float2(*(const __half2*)&a00);
        float2 f01 = __half22float2(*(const __half2*)&a01);
        float2 f10 = __half22float2(*(const __half2*)&a10);
        float2 f11 = __half22float2(*(const __half2*)&a11);
        acc[2*h+0] += f00.x * w00 + f01.x * w01 + f10.x * w10 + f11.x * w11;
        acc[2*h+1] += f00.y * w00 + f01.y * w01 + f10.y * w10 + f11.y * w11;
    }
}

__device__ __forceinline__ void decode_item(
    const float* __restrict__ pts, int gid,
    int& p, int& k, float& cx, float& cy, float*& outrow, float* out)
{
    const int n = gid / THREADS_PER_PT;
    const int j = gid - n * THREADS_PER_PT;
    p = j / NCHUNK_H;
    k = j - p * NCHUNK_H;

    const float d0 = -0.625f * __ldg(&pts[3 * n + 0]);
    const float d1 = -0.625f * __ldg(&pts[3 * n + 1]);
    const float d2 = -0.625f * __ldg(&pts[3 * n + 2]);
    cx = (p == 2) ? d1 : d0;
    cy = (p == 0) ? d1 : d2;

    outrow = out + (size_t)n * 864 + p * CDIM + k * 8;
}

// ---------------- persistent gather ----------------
__global__ __launch_bounds__(256, 3) void gather_k(
    const float* __restrict__ pts, float* __restrict__ out, int N)
{
    const int total  = N * THREADS_PER_PT;
    const int stride = GATHER_BLOCKS * 256;
    const int start  = blockIdx.x * 256 + threadIdx.x;

    const int resos[3] = {64, 128, 256};
    const int offs[3]  = {0, 884736, 4423680};

    // wait for the small transposes (side stream 2)
    if (threadIdx.x == 0) {
        while (atomicAdd(&g_small, 0) < SMALL_TOTAL) __nanosleep(64);
        __threadfence();
    }
    __syncthreads();

    // phase A: sample scales 0-2, write output blocks 0-2 (overlaps s3 transpose)
    for (int gid = start; gid < total; gid += stride) {
        int p, k; float cx, cy; float* outrow;
        decode_item(pts, gid, p, k, cx, cy, outrow, out);

        float acc[8];
        #pragma unroll
        for (int i = 0; i < 8; i++) acc[i] = 0.0f;

        #pragma unroll
        for (int s = 0; s < 3; s++) {
            sample_scale(p, k, cx, cy, resos[s], g_tph + offs[s], acc);
            __stcs((float4*)(outrow + s * 216),
                   make_float4(acc[0], acc[1], acc[2], acc[3]));
            __stcs((float4*)(outrow + s * 216) + 1,
                   make_float4(acc[4], acc[5], acc[6], acc[7]));
        }
    }

    // wait for the s3 transpose (side stream 1)
    if (threadIdx.x == 0) {
        while (atomicAdd(&g_s3, 0) < S3_TOTAL) __nanosleep(128);
        __threadfence();
    }
    __syncthreads();

    // phase B: recompute s0-2 in registers (L2-resident tables), add s3, write block 3
    for (int gid = start; gid < total; gid += stride) {
        int p, k; float cx, cy; float* outrow;
        decode_item(pts, gid, p, k, cx, cy, outrow, out);

        float acc[8];
        #pragma unroll
        for (int i = 0; i < 8; i++) acc[i] = 0.0f;

        #pragma unroll
        for (int s = 0; s < 3; s++)
            sample_scale(p, k, cx, cy, resos[s], g_tph + offs[s], acc);
        sample_scale(p, k, cx, cy, 512, g_tph + 18579456, acc);

        __stcs((float4*)(outrow + 3 * 216),
               make_float4(acc[0], acc[1], acc[2], acc[3]));
        __stcs((float4*)(outrow + 3 * 216) + 1,
               make_float4(acc[4], acc[5], acc[6], acc[7]));
    }

    // replay-safe reset: last gather block zeroes the counters
    __syncthreads();
    if (threadIdx.x == 0) {
        int f = atomicAdd(&g_fin, 1);
        if (f == GATHER_BLOCKS - 1) {
            atomicExch(&g_s3, 0);
            atomicExch(&g_small, 0);
            atomicExch(&g_fin, 0);
        }
    }
}

__device__ int* get_ctr_s3()    { return &g_s3; }

extern "C" void kernel_launch(void* const* d_in, const int* in_sizes, int n_in,
                              void* d_out, int out_size)
{
    const float* pts = (const float*)d_in[0];
    const int N = in_sizes[0] / 3;
    float* out = (float*)d_out;

    static const int res[4]  = {64, 128, 256, 512};
    static const int offs[4] = {0, 884736, 4423680, 18579456};

    static cudaStream_t s_s1 = nullptr, s_s2 = nullptr;
    static cudaEvent_t  s_ev_fork = nullptr, s_ev_j1 = nullptr, s_ev_j2 = nullptr;
    static int* s_ctr_s3 = nullptr;
    static int* s_ctr_small = nullptr;
    static bool s_init = false;
    if (!s_init) {
        s_init = true;
        cudaStreamCreateWithFlags(&s_s1, cudaStreamNonBlocking);
        cudaStreamCreateWithFlags(&s_s2, cudaStreamNonBlocking);
        cudaEventCreateWithFlags(&s_ev_fork, cudaEventDisableTiming);
        cudaEventCreateWithFlags(&s_ev_j1, cudaEventDisableTiming);
        cudaEventCreateWithFlags(&s_ev_j2, cudaEventDisableTiming);
        cudaGetSymbolAddress((void**)&s_ctr_s3, g_s3);
        cudaGetSymbolAddress((void**)&s_ctr_small, g_small);
    }

    // fork both side streams from the capture stream
    cudaEventRecord(s_ev_fork, 0);
    cudaStreamWaitEvent(s_s1, s_ev_fork, 0);
    cudaStreamWaitEvent(s_s2, s_ev_fork, 0);

    // side stream 1: big s3 transpose
    {
        const float* g = (const float*)d_in[4];
        const int r2 = 512 * 512;
        dim3 grid(r2 / 64, 3);
        transpose_k<<<grid, 288, 0, s_s1>>>(g, offs[3], r2, s_ctr_s3);
    }
    // side stream 2: small transposes
    for (int s = 0; s < 3; s++) {
        const float* g = (const float*)d_in[1 + s];
        const int r2 = res[s] * res[s];
        dim3 grid(r2 / 64, 3);
        transpose_k<<<grid, 288, 0, s_s2>>>(g, offs[s], r2, s_ctr_small);
    }

    // capture stream: persistent gather (flag-gated internally)
    gather_k<<<GATHER_BLOCKS, 256>>>(pts, out, N);

    // join both side streams after gather (capture validity; no added dep)
    cudaEventRecord(s_ev_j1, s_s1);
    cudaStreamWaitEvent(0, s_ev_j1, 0);
    cudaEventRecord(s_ev_j2, s_s2);
    cudaStreamWaitEvent(0, s_ev_j2, 0);
}

// round 17
// speedup vs baseline: 2.7526x; 2.7526x over previous
#include <cuda_runtime.h>
#include <cuda_fp16.h>

// Triplane sampling, GB300 (sm_103a).
// capture stream: transpose s0,s1,s2 -> gather (samples s0-2 with batched
//                 loads, writes blocks 0-2, flag-waits for s3, samples s3)
// side stream:    transpose s3 (fp32->fp16, 339MB); blocks bump g_done
// fp16 channel-major scratch [scale][plane][texel][72] halves (150 MB).

#define CDIM 72
#define NCHUNK_H 9           // 72 / 8 halves per uint4 chunk
#define THREADS_PER_PT 27    // 3 planes * 9 chunks
#define S3_BLOCKS (4096 * 3) // s3 transpose grid (r2/64, 3)

__device__ __half g_tph[75202560];   // 150.4 MB fp16 scratch, channel-major
__device__ int    g_done = 0;        // s3 transpose blocks completed
__device__ int    g_fin  = 0;        // gather blocks completed (for reset)

__device__ __forceinline__ unsigned h2_bits(__half2 h) {
    union { __half2 h; unsigned u; } cv;
    cv.h = h;
    return cv.u;
}

// ---------------- transpose: [3,72,r2] fp32 -> [3, r2, 72] fp16 ----------------
__global__ __launch_bounds__(288) void transpose_k(
    const float* __restrict__ in, int off, int r2, int notify)
{
    __shared__ unsigned tile[36 * 68];   // [ch-pair][texel], row pad 68
    const int p   = blockIdx.y;
    const int t0  = blockIdx.x * 64;
    const int tid = threadIdx.x;

    const float* src = in + (size_t)p * CDIM * r2 + t0;
    #pragma unroll
    for (int i = 0; i < 2; i++) {
        int idx = i * 288 + tid;         // 0..575
        int v   = idx & 15;              // texel quad 0..15
        int cp  = idx >> 4;              // channel pair 0..35
        const float* sp = src + (size_t)(2 * cp) * r2 + 4 * v;
        float4 a = __ldg((const float4*)sp);
        float4 b = __ldg((const float4*)(sp + r2));
        uint4 o;
        o.x = h2_bits(__floats2half2_rn(a.x, b.x));
        o.y = h2_bits(__floats2half2_rn(a.y, b.y));
        o.z = h2_bits(__floats2half2_rn(a.z, b.z));
        o.w = h2_bits(__floats2half2_rn(a.w, b.w));
        *(uint4*)&tile[cp * 68 + 4 * v] = o;
    }
    __syncthreads();

    uint4* dst = (uint4*)(g_tph + off) + ((size_t)p * r2 + t0) * NCHUNK_H;
    #pragma unroll
    for (int i = 0; i < 2; i++) {
        int lin = i * 288 + tid;         // 0..575
        int x = lin / NCHUNK_H;          // texel 0..63
        int q = lin - x * NCHUNK_H;      // uint4 index 0..8
        uint4 o;
        o.x = tile[(4 * q + 0) * 68 + x];
        o.y = tile[(4 * q + 1) * 68 + x];
        o.z = tile[(4 * q + 2) * 68 + x];
        o.w = tile[(4 * q + 3) * 68 + x];
        dst[lin] = o;
    }

    if (notify) {
        __syncthreads();
        if (tid == 0) {
            __threadfence();
            atomicAdd(&g_done, 1);
        }
    }
}

// ---------------- corner address/weight setup for one scale ----------------
struct ScaleSamp {
    const uint4 *a00, *a01, *a10, *a11;
    float w00, w01, w10, w11;
};

__device__ __forceinline__ ScaleSamp setup_scale(
    int p, int k, float cx, float cy, int r, const __half* __restrict__ base)
{
    const float rm1 = (float)(r - 1);
    float fx = (cx + 1.0f) * 0.5f * rm1;
    float fy = (cy + 1.0f) * 0.5f * rm1;
    fx = fminf(fmaxf(fx, 0.0f), rm1);
    fy = fminf(fmaxf(fy, 0.0f), rm1);

    const float x0f = floorf(fx);
    const float y0f = floorf(fy);
    const float wx = fx - x0f;
    const float wy = fy - y0f;
    const int x0 = (int)x0f;
    const int y0 = (int)y0f;
    const int x1 = min(x0 + 1, r - 1);
    const int y1 = min(y0 + 1, r - 1);

    const unsigned row0 = (unsigned)(p * r + y0) * (unsigned)r;
    const unsigned row1 = (unsigned)(p * r + y1) * (unsigned)r;

    ScaleSamp s;
    s.a00 = (const uint4*)(base + (size_t)(row0 + x0) * CDIM) + k;
    s.a01 = (const uint4*)(base + (size_t)(row0 + x1) * CDIM) + k;
    s.a10 = (const uint4*)(base + (size_t)(row1 + x0) * CDIM) + k;
    s.a11 = (const uint4*)(base + (size_t)(row1 + x1) * CDIM) + k;
    s.w00 = (1.0f - wx) * (1.0f - wy);
    s.w01 = wx * (1.0f - wy);
    s.w10 = (1.0f - wx) * wy;
    s.w11 = wx * wy;
    return s;
}

__device__ __forceinline__ void accum_corners(
    const uint4& u00, const uint4& u01, const uint4& u10, const uint4& u11,
    const ScaleSamp& s, float* acc)
{
    #pragma unroll
    for (int h = 0; h < 4; h++) {
        const unsigned a00 = (&u00.x)[h], a01 = (&u01.x)[h];
        const unsigned a10 = (&u10.x)[h], a11 = (&u11.x)[h];
        float2 f00 = __half22float2(*(const __half2*)&a00);
        float2 f01 = __half22float2(*(const __half2*)&a01);
        float2 f10 = __half22float2(*(const __half2*)&a10);
        float2 f11 = __half22float2(*(const __half2*)&a11);
        acc[2*h+0] += f00.x * s.w00 + f01.x * s.w01 + f10.x * s.w10 + f11.x * s.w11;
        acc[2*h+1] += f00.y * s.w00 + f01.y * s.w01 + f10.y * s.w10 + f11.y * s.w11;
    }
}

// ---------------- gather (batched loads for MLP; flag-fused with s3) ----------
__global__ __launch_bounds__(256) void gather_k(
    const float* __restrict__ pts, float* __restrict__ out, int N)
{
    const int gid = blockIdx.x * blockDim.x + threadIdx.x;
    const int total = N * THREADS_PER_PT;
    const bool valid = (gid < total);

    int p = 0, k = 0;
    float cx = 0.f, cy = 0.f;
    float* outrow = out;
    float acc[8];
    #pragma unroll
    for (int i = 0; i < 8; i++) acc[i] = 0.0f;

    if (valid) {
        const int n = gid / THREADS_PER_PT;
        const int j = gid - n * THREADS_PER_PT;
        p = j / NCHUNK_H;
        k = j - p * NCHUNK_H;

        const float d0 = -0.625f * __ldg(&pts[3 * n + 0]);
        const float d1 = -0.625f * __ldg(&pts[3 * n + 1]);
        const float d2 = -0.625f * __ldg(&pts[3 * n + 2]);
        cx = (p == 2) ? d1 : d0;
        cy = (p == 0) ? d1 : d2;

        outrow = out + (size_t)n * 864 + p * CDIM + k * 8;

        // setup all three small scales, then batch loads across scales
        ScaleSamp s0 = setup_scale(p, k, cx, cy, 64,  g_tph);
        ScaleSamp s1 = setup_scale(p, k, cx, cy, 128, g_tph + 884736);
        ScaleSamp s2 = setup_scale(p, k, cx, cy, 256, g_tph + 4423680);

        // issue 8 independent loads (scales 0 and 1)
        uint4 v0a = __ldg(s0.a00), v0b = __ldg(s0.a01),
              v0c = __ldg(s0.a10), v0d = __ldg(s0.a11);
        uint4 v1a = __ldg(s1.a00), v1b = __ldg(s1.a01),
              v1c = __ldg(s1.a10), v1d = __ldg(s1.a11);
        // issue scale 2's loads before consuming scale 0/1
        uint4 v2a = __ldg(s2.a00), v2b = __ldg(s2.a01),
              v2c = __ldg(s2.a10), v2d = __ldg(s2.a11);

        accum_corners(v0a, v0b, v0c, v0d, s0, acc);
        __stcs((float4*)(outrow + 0 * 216),
               make_float4(acc[0], acc[1], acc[2], acc[3]));
        __stcs((float4*)(outrow + 0 * 216) + 1,
               make_float4(acc[4], acc[5], acc[6], acc[7]));

        accum_corners(v1a, v1b, v1c, v1d, s1, acc);
        __stcs((float4*)(outrow + 1 * 216),
               make_float4(acc[0], acc[1], acc[2], acc[3]));
        __stcs((float4*)(outrow + 1 * 216) + 1,
               make_float4(acc[4], acc[5], acc[6], acc[7]));

        accum_corners(v2a, v2b, v2c, v2d, s2, acc);
        __stcs((float4*)(outrow + 2 * 216),
               make_float4(acc[0], acc[1], acc[2], acc[3]));
        __stcs((float4*)(outrow + 2 * 216) + 1,
               make_float4(acc[4], acc[5], acc[6], acc[7]));
    }

    // wait for the s3 transpose (runs concurrently on the side stream)
    if (threadIdx.x == 0) {
        while (atomicAdd(&g_done, 0) < S3_BLOCKS) __nanosleep(128);
        __threadfence();
    }
    __syncthreads();

    if (valid) {
        ScaleSamp s3 = setup_scale(p, k, cx, cy, 512, g_tph + 18579456);
        uint4 v3a = __ldg(s3.a00), v3b = __ldg(s3.a01),
              v3c = __ldg(s3.a10), v3d = __ldg(s3.a11);
        accum_corners(v3a, v3b, v3c, v3d, s3, acc);
        __stcs((float4*)(outrow + 3 * 216),
               make_float4(acc[0], acc[1], acc[2], acc[3]));
        __stcs((float4*)(outrow + 3 * 216) + 1,
               make_float4(acc[4], acc[5], acc[6], acc[7]));
    }

    // replay-safe reset: last gather block zeroes the counters
    __syncthreads();
    if (threadIdx.x == 0) {
        int f = atomicAdd(&g_fin, 1);
        if (f == (int)gridDim.x - 1) {
            atomicExch(&g_done, 0);
            atomicExch(&g_fin, 0);
        }
    }
}

extern "C" void kernel_launch(void* const* d_in, const int* in_sizes, int n_in,
                              void* d_out, int out_size)
{
    const float* pts = (const float*)d_in[0];
    const int N = in_sizes[0] / 3;
    float* out = (float*)d_out;

    static const int res[4]  = {64, 128, 256, 512};
    static const int offs[4] = {0, 884736, 4423680, 18579456};

    static cudaStream_t s_side = nullptr;
    static cudaEvent_t  s_ev_fork = nullptr, s_ev_join = nullptr;
    static bool s_init = false;
    if (!s_init) {
        s_init = true;
        if (cudaStreamCreateWithFlags(&s_side, cudaStreamNonBlocking) != cudaSuccess)
            s_side = nullptr;
        cudaEventCreateWithFlags(&s_ev_fork, cudaEventDisableTiming);
        cudaEventCreateWithFlags(&s_ev_join, cudaEventDisableTiming);
    }
    const bool fork = (s_side != nullptr && s_ev_fork && s_ev_join);
    cudaStream_t sb = fork ? s_side : (cudaStream_t)0;

    if (fork) {
        cudaEventRecord(s_ev_fork, 0);
        cudaStreamWaitEvent(sb, s_ev_fork, 0);
    }

    // Side stream: the big s3 transpose; blocks bump g_done as they finish.
    {
        const float* g = (const float*)d_in[4];
        const int r2 = 512 * 512;
        dim3 grid(r2 / 64, 3);
        transpose_k<<<grid, 288, 0, sb>>>(g, offs[3], r2, 1);
    }

    // Capture stream: small transposes, then gather (flag-waits for s3 inside).
    for (int s = 0; s < 3; s++) {
        const float* g = (const float*)d_in[1 + s];
        const int r2 = res[s] * res[s];
        dim3 grid(r2 / 64, 3);
        transpose_k<<<grid, 288>>>(g, offs[s], r2, 0);
    }
    const int total = N * THREADS_PER_PT;
    gather_k<<<(total + 255) / 256, 256>>>(pts, out, N);

    // Join side stream after gather (capture validity; no added dependency).
    if (fork) {
        cudaEventRecord(s_ev_join, sb);
        cudaStreamWaitEvent(0, s_ev_join, 0);
    }
}